// round 15
// baseline (speedup 1.0000x reference)
#include <cuda_runtime.h>
#include <cuda_bf16.h>
#include <math.h>
#include <cstdint>

#define NN   8192
#define EE   262144
#define HID  512
#define LAT  128

// ---------------- scratch (__device__ globals; no allocation) ----------------
__device__ float g_h0[NN * HID];                 // x @ W1
__device__ float g_hw[NN * 256];                 // h @ [Wmu|Wlv]  (pre-aggregation)
__device__ float g_dinv[NN];
__device__ int   g_deg[NN];
__device__ int   g_off[NN + 1];
__device__ int   g_cursor[NN];
__device__ int   g_src[EE];
__device__ __nv_bfloat16 g_zs[NN * 128];         // z hi-only bf16
__device__ __nv_bfloat16 g_hs[NN * 1024];        // h split (relu(agg(h0)+b1))
__device__ __nv_bfloat16 g_w1s[512 * 1024];      // W1^T split: [n][k-hi | k-lo]
__device__ __nv_bfloat16 g_wmls[256 * 1024];     // [Wmu^T ; Wlv^T] split

__device__ __forceinline__ uint32_t smem_to_u32(const void* smem_ptr) {
    uint32_t addr;
    asm("{ .reg .u64 tmp; cvta.to.shared.u64 tmp, %1; cvt.u32.u64 %0, tmp; }"
        : "=r"(addr) : "l"(smem_ptr));
    return addr;
}

__device__ __forceinline__ void split2(float v, __nv_bfloat16& hi, __nv_bfloat16& lo) {
    hi = __float2bfloat16(v);
    lo = __float2bfloat16(v - __bfloat162float(hi));
}

// ---------------- prep: split W1/Wmu/Wlv only (x handled inside gemm1) ----------------
__global__ void wsplit_kernel(const float* __restrict__ W1,
                              const float* __restrict__ Wmu, const float* __restrict__ Wlv,
                              __nv_bfloat16* __restrict__ w1s,
                              __nv_bfloat16* __restrict__ wmls) {
    int i = blockIdx.x * blockDim.x + threadIdx.x;   // 0 .. 512*512-1
    {
        int k = i >> 9, n = i & 511;
        __nv_bfloat16 hi, lo;
        split2(W1[i], hi, lo);
        w1s[(size_t)n * 1024 + k] = hi;
        w1s[(size_t)n * 1024 + 512 + k] = lo;
    }
    if (i < 512 * 128) {
        int k = i >> 7, n = i & 127;
        __nv_bfloat16 hi, lo;
        split2(Wmu[i], hi, lo);
        wmls[(size_t)n * 1024 + k] = hi;
        wmls[(size_t)n * 1024 + 512 + k] = lo;
        split2(Wlv[i], hi, lo);
        wmls[(size_t)(n + 128) * 1024 + k] = hi;
        wmls[(size_t)(n + 128) * 1024 + 512 + k] = lo;
    }
}

// ---------------- graph preprocessing (aux-stream chain) ----------------
__global__ void zero_kernel() {
    int i = blockIdx.x * blockDim.x + threadIdx.x;
    if (i < NN) { g_deg[i] = 0; g_cursor[i] = 0; }
}

__global__ void count_kernel(const int* __restrict__ col) {
    int e = blockIdx.x * blockDim.x + threadIdx.x;
    if (e < EE) atomicAdd(&g_deg[col[e]], 1);
}

__global__ void scan_kernel() {
    __shared__ int wtot[32];
    int t = threadIdx.x, lane = t & 31, w = t >> 5;
    int base = t * 8;
    int d[8], pre[8];
    int sum = 0;
    #pragma unroll
    for (int i = 0; i < 8; i++) { d[i] = g_deg[base + i]; pre[i] = sum; sum += d[i]; }
    int v = sum;
    #pragma unroll
    for (int off = 1; off < 32; off <<= 1) {
        int n = __shfl_up_sync(0xffffffffu, v, off);
        if (lane >= off) v += n;
    }
    if (lane == 31) wtot[w] = v;
    __syncthreads();
    if (w == 0) {
        int x = wtot[lane];
        int y = x;
        #pragma unroll
        for (int off = 1; off < 32; off <<= 1) {
            int n = __shfl_up_sync(0xffffffffu, y, off);
            if (lane >= off) y += n;
        }
        wtot[lane] = y - x;
    }
    __syncthreads();
    int excl = v - sum + wtot[w];
    #pragma unroll
    for (int i = 0; i < 8; i++) g_off[base + i] = excl + pre[i];
    #pragma unroll
    for (int i = 0; i < 8; i++) g_dinv[base + i] = rsqrtf((float)(d[i] + 1));
    if (t == 1023) g_off[NN] = excl + sum;
}

__global__ void fill_kernel(const int* __restrict__ row, const int* __restrict__ col) {
    int e = blockIdx.x * blockDim.x + threadIdx.x;
    if (e < EE) {
        int c = col[e];
        int pos = g_off[c] + atomicAdd(&g_cursor[c], 1);
        g_src[pos] = row[e];
    }
}

// ---------------- pass 1: h = relu(agg(h0) + b1), emitted as bf16 split ----------------
__global__ void aggregate_relu_split_kernel(const float* __restrict__ H,
                                            const float* __restrict__ bias,
                                            __nv_bfloat16* __restrict__ outs) {
    int node = blockIdx.x;
    int f = threadIdx.x * 4;
    float di = g_dinv[node];
    int s0 = g_off[node], s1 = g_off[node + 1];
    float4 acc = make_float4(0.f, 0.f, 0.f, 0.f);
    for (int e = s0; e < s1; e++) {
        int s = g_src[e];
        float w = g_dinv[s];
        float4 v = *(const float4*)&H[(size_t)s * HID + f];
        acc.x += w * v.x; acc.y += w * v.y; acc.z += w * v.z; acc.w += w * v.w;
    }
    float4 hv = *(const float4*)&H[(size_t)node * HID + f];
    float4 b = *(const float4*)&bias[f];
    float r[4];
    r[0] = fmaxf(di * acc.x + di * di * hv.x + b.x, 0.f);
    r[1] = fmaxf(di * acc.y + di * di * hv.y + b.y, 0.f);
    r[2] = fmaxf(di * acc.z + di * di * hv.z + b.z, 0.f);
    r[3] = fmaxf(di * acc.w + di * di * hv.w + b.w, 0.f);
    size_t rb = (size_t)node * 1024 + f;
    #pragma unroll
    for (int j = 0; j < 4; j++) {
        __nv_bfloat16 hi, lo;
        split2(r[j], hi, lo);
        outs[rb + j] = hi;
        outs[rb + 512 + j] = lo;
    }
}

// ---------------- pass 2: final 256-wide aggregation of hw -> mu/z/lv/zs ----------------
__global__ void final_agg_kernel(const float* __restrict__ HW,
                                 const float* __restrict__ bmu, const float* __restrict__ blv,
                                 float* __restrict__ mu, float* __restrict__ z,
                                 float* __restrict__ lv, __nv_bfloat16* __restrict__ zs) {
    int node = blockIdx.x;
    int f = threadIdx.x * 4;                 // 64 threads * 4 = 256
    float di = g_dinv[node];
    int s0 = g_off[node], s1 = g_off[node + 1];
    float4 acc = make_float4(0.f, 0.f, 0.f, 0.f);
    for (int e = s0; e < s1; e++) {
        int s = g_src[e];
        float w = g_dinv[s];
        float4 v = *(const float4*)&HW[(size_t)s * 256 + f];
        acc.x += w * v.x; acc.y += w * v.y; acc.z += w * v.z; acc.w += w * v.w;
    }
    float4 hv = *(const float4*)&HW[(size_t)node * 256 + f];
    float4 r;
    r.x = di * acc.x + di * di * hv.x;
    r.y = di * acc.y + di * di * hv.y;
    r.z = di * acc.z + di * di * hv.z;
    r.w = di * acc.w + di * di * hv.w;
    if (f < 128) {
        float4 b = *(const float4*)&bmu[f];
        r.x += b.x; r.y += b.y; r.z += b.z; r.w += b.w;
        size_t o = (size_t)node * LAT + f;
        *(float4*)&mu[o] = r;
        *(float4*)&z[o] = r;
        __nv_bfloat162 p0, p1;
        p0.x = __float2bfloat16(r.x); p0.y = __float2bfloat16(r.y);
        p1.x = __float2bfloat16(r.z); p1.y = __float2bfloat16(r.w);
        *(__nv_bfloat162*)&zs[o] = p0;
        *(__nv_bfloat162*)&zs[o + 2] = p1;
    } else {
        float4 b = *(const float4*)&blv[f - 128];
        r.x += b.x; r.y += b.y; r.z += b.z; r.w += b.w;
        *(float4*)&lv[(size_t)node * LAT + f - 128] = r;
    }
}

// ---------------- MMA primitives ----------------
__device__ __forceinline__ void ldsm_x4(uint32_t& r0, uint32_t& r1, uint32_t& r2, uint32_t& r3,
                                        uint32_t addr) {
    asm volatile("ldmatrix.sync.aligned.m8n8.x4.shared.b16 {%0,%1,%2,%3}, [%4];"
                 : "=r"(r0), "=r"(r1), "=r"(r2), "=r"(r3) : "r"(addr));
}

__device__ __forceinline__ void mma_bf16(float* c, const uint32_t* a, const uint32_t* b) {
    asm volatile(
        "mma.sync.aligned.m16n8k16.row.col.f32.bf16.bf16.f32 "
        "{%0,%1,%2,%3}, {%4,%5,%6,%7}, {%8,%9}, {%0,%1,%2,%3};"
        : "+f"(c[0]), "+f"(c[1]), "+f"(c[2]), "+f"(c[3])
        : "r"(a[0]), "r"(a[1]), "r"(a[2]), "r"(a[3]), "r"(b[0]), "r"(b[1]));
}

// ---------------- gemm1: h0 = x @ W1^T-split, A read as fp32 + in-register split ----------------
__global__ __launch_bounds__(256) void mma_gemm_xf32(
    const float* __restrict__ X, const __nv_bfloat16* __restrict__ B,
    float* __restrict__ C0) {
    constexpr int KPART = 512;
    constexpr int CPK = KPART / 64;          // 8
    constexpr int NSTEP = 3 * CPK;           // 24

    __shared__ __nv_bfloat16 As[128 * 64];
    __shared__ __nv_bfloat16 Bs[128 * 64];
    int tid = threadIdx.x;
    int wid = tid >> 5;
    int lane = tid & 31;
    int wm = wid & 3;
    int wn = wid >> 2;

    const float* Abase = X + (size_t)(blockIdx.y * 128) * KPART;
    const __nv_bfloat16* Bbase = B + (size_t)(blockIdx.x * 128) * (2 * KPART);
    uint32_t as_u = smem_to_u32(As);
    uint32_t bs_u = smem_to_u32(Bs);

    float acc[2][8][4] = {};

    for (int step = 0; step < NSTEP; step++) {
        int p = step / CPK;
        int kk = step % CPK;
        int alo = (p == 2);
        int boff = (p == 1) ? KPART : 0;
        #pragma unroll
        for (int i = 0; i < 4; i++) {
            int cid = tid + i * 256;
            int row = cid >> 3;
            int ch = cid & 7;
            int sw = (ch ^ (row & 7)) * 8;
            const float* src = Abase + (size_t)row * KPART + kk * 64 + ch * 8;
            float4 v0 = *(const float4*)src;
            float4 v1 = *(const float4*)(src + 4);
            float vs[8] = {v0.x, v0.y, v0.z, v0.w, v1.x, v1.y, v1.z, v1.w};
            __nv_bfloat16 b8[8];
            #pragma unroll
            for (int j = 0; j < 8; j++) {
                __nv_bfloat16 hi = __float2bfloat16(vs[j]);
                b8[j] = alo ? __float2bfloat16(vs[j] - __bfloat162float(hi)) : hi;
            }
            *(float4*)&As[row * 64 + sw] = *(float4*)b8;
            *(float4*)&Bs[row * 64 + sw] =
                *(const float4*)&Bbase[(size_t)row * (2 * KPART) + boff + kk * 64 + ch * 8];
        }
        __syncthreads();

        #pragma unroll
        for (int ks = 0; ks < 4; ks++) {
            uint32_t a[2][4];
            #pragma unroll
            for (int mt = 0; mt < 2; mt++) {
                int row = wm * 32 + mt * 16 + (lane & 15);
                int ch = ks * 2 + (lane >> 4);
                uint32_t addr = as_u + row * 128 + ((ch ^ (row & 7)) << 4);
                ldsm_x4(a[mt][0], a[mt][1], a[mt][2], a[mt][3], addr);
            }
            uint32_t b[8][2];
            #pragma unroll
            for (int q = 0; q < 4; q++) {
                int grp = lane >> 3;
                int nrow = wn * 64 + q * 16 + ((grp >> 1) << 3) + (lane & 7);
                int ch = ks * 2 + (grp & 1);
                uint32_t addr = bs_u + nrow * 128 + ((ch ^ (nrow & 7)) << 4);
                ldsm_x4(b[q * 2][0], b[q * 2][1], b[q * 2 + 1][0], b[q * 2 + 1][1], addr);
            }
            #pragma unroll
            for (int mt = 0; mt < 2; mt++)
                #pragma unroll
                for (int nt = 0; nt < 8; nt++)
                    mma_bf16(acc[mt][nt], a[mt], b[nt]);
        }
        __syncthreads();
    }

    int rbase = blockIdx.y * 128 + wm * 32 + (lane >> 2);
    int cloc = wn * 64 + (lane & 3) * 2;
    #pragma unroll
    for (int mt = 0; mt < 2; mt++) {
        #pragma unroll
        for (int nt = 0; nt < 8; nt++) {
            float* c = acc[mt][nt];
            int gc = blockIdx.x * 128 + cloc + nt * 8;
            #pragma unroll
            for (int rr = 0; rr < 2; rr++) {
                size_t row = (size_t)(rbase + mt * 16 + rr * 8);
                *(float2*)&C0[row * 512 + gc] = make_float2(c[rr * 2 + 0], c[rr * 2 + 1]);
            }
        }
    }
}

// ---------------- gemm2: C = A @ B^T, pre-split A & B, 3 phases ----------------
template<int KPART, int PHASES>
__global__ __launch_bounds__(256) void mma_gemm(
    const __nv_bfloat16* __restrict__ A, const __nv_bfloat16* __restrict__ B,
    float* __restrict__ C0, int ldc) {
    constexpr int RS = (PHASES == 3 ? 2 : 1) * KPART;
    constexpr int CPK = KPART / 64;
    constexpr int NSTEP = PHASES * CPK;

    __shared__ __nv_bfloat16 As[128 * 64];
    __shared__ __nv_bfloat16 Bs[128 * 64];
    int tid = threadIdx.x;
    int wid = tid >> 5;
    int lane = tid & 31;
    int wm = wid & 3;
    int wn = wid >> 2;

    const __nv_bfloat16* Abase = A + (size_t)(blockIdx.y * 128) * RS;
    const __nv_bfloat16* Bbase = B + (size_t)(blockIdx.x * 128) * RS;
    uint32_t as_u = smem_to_u32(As);
    uint32_t bs_u = smem_to_u32(Bs);

    float acc[2][8][4] = {};

    for (int step = 0; step < NSTEP; step++) {
        int p = step / CPK;
        int kk = step % CPK;
        int aoff = (PHASES == 3 && p == 2) ? KPART : 0;
        int boff = (PHASES == 3 && p == 1) ? KPART : 0;
        #pragma unroll
        for (int i = 0; i < 4; i++) {
            int cid = tid + i * 256;
            int row = cid >> 3;
            int ch = cid & 7;
            int sw = (ch ^ (row & 7)) * 8;
            *(float4*)&As[row * 64 + sw] =
                *(const float4*)&Abase[(size_t)row * RS + aoff + kk * 64 + ch * 8];
            *(float4*)&Bs[row * 64 + sw] =
                *(const float4*)&Bbase[(size_t)row * RS + boff + kk * 64 + ch * 8];
        }
        __syncthreads();

        #pragma unroll
        for (int ks = 0; ks < 4; ks++) {
            uint32_t a[2][4];
            #pragma unroll
            for (int mt = 0; mt < 2; mt++) {
                int row = wm * 32 + mt * 16 + (lane & 15);
                int ch = ks * 2 + (lane >> 4);
                uint32_t addr = as_u + row * 128 + ((ch ^ (row & 7)) << 4);
                ldsm_x4(a[mt][0], a[mt][1], a[mt][2], a[mt][3], addr);
            }
            uint32_t b[8][2];
            #pragma unroll
            for (int q = 0; q < 4; q++) {
                int grp = lane >> 3;
                int nrow = wn * 64 + q * 16 + ((grp >> 1) << 3) + (lane & 7);
                int ch = ks * 2 + (grp & 1);
                uint32_t addr = bs_u + nrow * 128 + ((ch ^ (nrow & 7)) << 4);
                ldsm_x4(b[q * 2][0], b[q * 2][1], b[q * 2 + 1][0], b[q * 2 + 1][1], addr);
            }
            #pragma unroll
            for (int mt = 0; mt < 2; mt++)
                #pragma unroll
                for (int nt = 0; nt < 8; nt++)
                    mma_bf16(acc[mt][nt], a[mt], b[nt]);
        }
        __syncthreads();
    }

    int rbase = blockIdx.y * 128 + wm * 32 + (lane >> 2);
    int cloc = wn * 64 + (lane & 3) * 2;
    #pragma unroll
    for (int mt = 0; mt < 2; mt++) {
        #pragma unroll
        for (int nt = 0; nt < 8; nt++) {
            float* c = acc[mt][nt];
            int gc = blockIdx.x * 128 + cloc + nt * 8;
            #pragma unroll
            for (int rr = 0; rr < 2; rr++) {
                size_t row = (size_t)(rbase + mt * 16 + rr * 8);
                *(float2*)&C0[row * ldc + gc] = make_float2(c[rr * 2 + 0], c[rr * 2 + 1]);
            }
        }
    }
}

// ---------------- band-persistent zzt: A_pred = sigmoid(Z @ Z^T) ----------------
// grid (4, 64): each CTA owns row band blockIdx.y (A-tile resident in SMEM, loaded once)
// and processes 16 column tiles (blockIdx.x*16 .. +15), streaming B-tiles.
// Full-K tiles (128 rows x 128 K bf16 = 32KB each); 64KB dynamic SMEM; occ 2.
#define ZZT_SMEM (2 * 128 * 128 * 2)

__global__ __launch_bounds__(256, 2) void zzt_band_kernel(const __nv_bfloat16* __restrict__ Zs,
                                                          float* __restrict__ out) {
    extern __shared__ __nv_bfloat16 zsm[];
    __nv_bfloat16* As = zsm;                 // 128 x 128 (row stride 128 elems, 16 chunks)
    __nv_bfloat16* Bs = zsm + 128 * 128;
    int tid = threadIdx.x;
    int wid = tid >> 5;
    int lane = tid & 31;
    int wm = wid & 3;
    int wn = wid >> 2;
    uint32_t as_u = smem_to_u32(As);
    uint32_t bs_u = smem_to_u32(Bs);

    // load A band once (full K)
    const __nv_bfloat16* Abase = Zs + (size_t)(blockIdx.y * 128) * 128;
    #pragma unroll
    for (int it = 0; it < 8; it++) {
        int cid = tid + it * 256;            // 0..2047
        int row = cid >> 4;
        int ch = cid & 15;
        int sw = (ch & 8) | ((ch & 7) ^ (row & 7));
        *(float4*)&As[row * 128 + sw * 8] =
            *(const float4*)&Abase[(size_t)row * 128 + ch * 8];
    }

    int rbase = blockIdx.y * 128 + wm * 32 + (lane >> 2);

    for (int ct = 0; ct < 16; ct++) {
        int colTile = blockIdx.x * 16 + ct;
        const __nv_bfloat16* Bbase = Zs + (size_t)colTile * 128 * 128;
        __syncthreads();                     // prior Bs readers done (also fences A stores)
        #pragma unroll
        for (int it = 0; it < 8; it++) {
            int cid = tid + it * 256;
            int row = cid >> 4;
            int ch = cid & 15;
            int sw = (ch & 8) | ((ch & 7) ^ (row & 7));
            *(float4*)&Bs[row * 128 + sw * 8] =
                *(const float4*)&Bbase[(size_t)row * 128 + ch * 8];
        }
        __syncthreads();

        float acc[2][8][4] = {};
        #pragma unroll
        for (int ks = 0; ks < 8; ks++) {
            uint32_t a[2][4];
            #pragma unroll
            for (int mt = 0; mt < 2; mt++) {
                int row = wm * 32 + mt * 16 + (lane & 15);
                int ch = ks * 2 + (lane >> 4);
                int sw = (ch & 8) | ((ch & 7) ^ (row & 7));
                uint32_t addr = as_u + row * 256 + sw * 16;
                ldsm_x4(a[mt][0], a[mt][1], a[mt][2], a[mt][3], addr);
            }
            uint32_t bfr[8][2];
            #pragma unroll
            for (int q = 0; q < 4; q++) {
                int grp = lane >> 3;
                int nrow = wn * 64 + q * 16 + ((grp >> 1) << 3) + (lane & 7);
                int ch = ks * 2 + (grp & 1);
                int sw = (ch & 8) | ((ch & 7) ^ (nrow & 7));
                uint32_t addr = bs_u + nrow * 256 + sw * 16;
                ldsm_x4(bfr[q * 2][0], bfr[q * 2][1], bfr[q * 2 + 1][0], bfr[q * 2 + 1][1], addr);
            }
            #pragma unroll
            for (int mt = 0; mt < 2; mt++)
                #pragma unroll
                for (int nt = 0; nt < 8; nt++)
                    mma_bf16(acc[mt][nt], a[mt], bfr[nt]);
        }

        int cbase = colTile * 128 + wn * 64 + (lane & 3) * 2;
        #pragma unroll
        for (int mt = 0; mt < 2; mt++) {
            #pragma unroll
            for (int nt = 0; nt < 8; nt++) {
                float* c = acc[mt][nt];
                size_t r0 = (size_t)(rbase + mt * 16);
                size_t c0 = (size_t)(cbase + nt * 8);
                float2 v0, v1;
                v0.x = 1.f / (1.f + __expf(-c[0]));
                v0.y = 1.f / (1.f + __expf(-c[1]));
                v1.x = 1.f / (1.f + __expf(-c[2]));
                v1.y = 1.f / (1.f + __expf(-c[3]));
                *(float2*)&out[r0 * NN + c0] = v0;
                *(float2*)&out[(r0 + 8) * NN + c0] = v1;
            }
        }
    }
}

// ---------------- aux stream/events (created once, on the non-captured first call) ----------------
struct Aux {
    cudaStream_t s2;
    cudaEvent_t  e_fork, e_join;
    Aux() {
        cudaStreamCreateWithFlags(&s2, cudaStreamNonBlocking);
        cudaEventCreateWithFlags(&e_fork, cudaEventDisableTiming);
        cudaEventCreateWithFlags(&e_join, cudaEventDisableTiming);
        cudaFuncSetAttribute(zzt_band_kernel,
                             cudaFuncAttributeMaxDynamicSharedMemorySize, ZZT_SMEM);
    }
};
static Aux& aux() { static Aux a; return a; }

// ---------------- launch ----------------
extern "C" void kernel_launch(void* const* d_in, const int* in_sizes, int n_in,
                              void* d_out, int out_size) {
    const int*   edge = (const int*)d_in[0];
    const float* x    = (const float*)d_in[1];
    const float* W1   = (const float*)d_in[2];
    const float* b1   = (const float*)d_in[3];
    const float* Wmu  = (const float*)d_in[4];
    const float* bmu  = (const float*)d_in[5];
    const float* Wlv  = (const float*)d_in[6];
    const float* blv  = (const float*)d_in[7];

    const int* row = edge;
    const int* col = edge + EE;

    float* out     = (float*)d_out;
    float* A_pred  = out;
    float* mu_out  = out + (size_t)NN * NN;
    float* lv_out  = mu_out + (size_t)NN * LAT;
    float* z_out   = lv_out + (size_t)NN * LAT;

    float* h0;   cudaGetSymbolAddress((void**)&h0,   g_h0);
    float* hw;   cudaGetSymbolAddress((void**)&hw,   g_hw);
    __nv_bfloat16* zs;   cudaGetSymbolAddress((void**)&zs,   g_zs);
    __nv_bfloat16* hs;   cudaGetSymbolAddress((void**)&hs,   g_hs);
    __nv_bfloat16* w1s;  cudaGetSymbolAddress((void**)&w1s,  g_w1s);
    __nv_bfloat16* wmls; cudaGetSymbolAddress((void**)&wmls, g_wmls);

    Aux& a = aux();

    // fork: aux stream runs graph preproc in parallel with wsplit+gemm1
    cudaEventRecord(a.e_fork, 0);
    cudaStreamWaitEvent(a.s2, a.e_fork, 0);
    zero_kernel<<<(NN + 255) / 256, 256, 0, a.s2>>>();
    count_kernel<<<(EE + 255) / 256, 256, 0, a.s2>>>(col);
    scan_kernel<<<1, 1024, 0, a.s2>>>();
    fill_kernel<<<(EE + 255) / 256, 256, 0, a.s2>>>(row, col);
    cudaEventRecord(a.e_join, a.s2);

    // main stream: weight splits (tiny), then layer-1 GEMM reading x fp32 directly
    wsplit_kernel<<<(512 * 512) / 256, 256>>>(W1, Wmu, Wlv, w1s, wmls);
    mma_gemm_xf32<<<dim3(4, 64), 256>>>(x, w1s, h0);

    // join: aggregation needs CSR (aux) + h0 (main)
    cudaStreamWaitEvent(0, a.e_join, 0);
    aggregate_relu_split_kernel<<<NN, 128>>>(h0, b1, hs);

    // layer 2: project first, aggregate 256-wide after
    mma_gemm<512, 3><<<dim3(2, 64), 256>>>(hs, wmls, hw, 256);
    final_agg_kernel<<<NN, 64>>>(hw, bmu, blv, mu_out, z_out, lv_out, zs);

    // decode: A_pred = sigmoid(z z^T), band-persistent (A-tile loaded once per band)
    zzt_band_kernel<<<dim3(4, 64), 256, ZZT_SMEM>>>(zs, A_pred);
}

// round 16
// speedup vs baseline: 1.0258x; 1.0258x over previous
#include <cuda_runtime.h>
#include <cuda_bf16.h>
#include <math.h>
#include <cstdint>

#define NN   8192
#define EE   262144
#define HID  512
#define LAT  128

// ---------------- scratch (__device__ globals; no allocation) ----------------
__device__ float g_h0[NN * HID];                 // x @ W1
__device__ float g_hw[NN * 256];                 // h @ [Wmu|Wlv]  (pre-aggregation)
__device__ float g_dinv[NN];
__device__ int   g_deg[NN];
__device__ int   g_off[NN + 1];
__device__ int   g_cursor[NN];
__device__ int   g_src[EE];
__device__ __nv_bfloat16 g_zs[NN * 128];         // z hi-only bf16
__device__ __nv_bfloat16 g_hs[NN * 1024];        // h split (relu(agg(h0)+b1))
__device__ __nv_bfloat16 g_w1s[512 * 1024];      // W1^T split: [n][k-hi | k-lo]
__device__ __nv_bfloat16 g_wmls[256 * 1024];     // [Wmu^T ; Wlv^T] split

__device__ __forceinline__ uint32_t smem_to_u32(const void* smem_ptr) {
    uint32_t addr;
    asm("{ .reg .u64 tmp; cvta.to.shared.u64 tmp, %1; cvt.u32.u64 %0, tmp; }"
        : "=r"(addr) : "l"(smem_ptr));
    return addr;
}

__device__ __forceinline__ void split2(float v, __nv_bfloat16& hi, __nv_bfloat16& lo) {
    hi = __float2bfloat16(v);
    lo = __float2bfloat16(v - __bfloat162float(hi));
}

// ---------------- prep: split W1/Wmu/Wlv only (x handled inside gemm1) ----------------
__global__ void wsplit_kernel(const float* __restrict__ W1,
                              const float* __restrict__ Wmu, const float* __restrict__ Wlv,
                              __nv_bfloat16* __restrict__ w1s,
                              __nv_bfloat16* __restrict__ wmls) {
    int i = blockIdx.x * blockDim.x + threadIdx.x;   // 0 .. 512*512-1
    {
        int k = i >> 9, n = i & 511;
        __nv_bfloat16 hi, lo;
        split2(W1[i], hi, lo);
        w1s[(size_t)n * 1024 + k] = hi;
        w1s[(size_t)n * 1024 + 512 + k] = lo;
    }
    if (i < 512 * 128) {
        int k = i >> 7, n = i & 127;
        __nv_bfloat16 hi, lo;
        split2(Wmu[i], hi, lo);
        wmls[(size_t)n * 1024 + k] = hi;
        wmls[(size_t)n * 1024 + 512 + k] = lo;
        split2(Wlv[i], hi, lo);
        wmls[(size_t)(n + 128) * 1024 + k] = hi;
        wmls[(size_t)(n + 128) * 1024 + 512 + k] = lo;
    }
}

// ---------------- graph preprocessing (aux-stream chain) ----------------
__global__ void zero_kernel() {
    int i = blockIdx.x * blockDim.x + threadIdx.x;
    if (i < NN) { g_deg[i] = 0; g_cursor[i] = 0; }
}

__global__ void count_kernel(const int* __restrict__ col) {
    int e = blockIdx.x * blockDim.x + threadIdx.x;
    if (e < EE) atomicAdd(&g_deg[col[e]], 1);
}

__global__ void scan_kernel() {
    __shared__ int wtot[32];
    int t = threadIdx.x, lane = t & 31, w = t >> 5;
    int base = t * 8;
    int d[8], pre[8];
    int sum = 0;
    #pragma unroll
    for (int i = 0; i < 8; i++) { d[i] = g_deg[base + i]; pre[i] = sum; sum += d[i]; }
    int v = sum;
    #pragma unroll
    for (int off = 1; off < 32; off <<= 1) {
        int n = __shfl_up_sync(0xffffffffu, v, off);
        if (lane >= off) v += n;
    }
    if (lane == 31) wtot[w] = v;
    __syncthreads();
    if (w == 0) {
        int x = wtot[lane];
        int y = x;
        #pragma unroll
        for (int off = 1; off < 32; off <<= 1) {
            int n = __shfl_up_sync(0xffffffffu, y, off);
            if (lane >= off) y += n;
        }
        wtot[lane] = y - x;
    }
    __syncthreads();
    int excl = v - sum + wtot[w];
    #pragma unroll
    for (int i = 0; i < 8; i++) g_off[base + i] = excl + pre[i];
    #pragma unroll
    for (int i = 0; i < 8; i++) g_dinv[base + i] = rsqrtf((float)(d[i] + 1));
    if (t == 1023) g_off[NN] = excl + sum;
}

__global__ void fill_kernel(const int* __restrict__ row, const int* __restrict__ col) {
    int e = blockIdx.x * blockDim.x + threadIdx.x;
    if (e < EE) {
        int c = col[e];
        int pos = g_off[c] + atomicAdd(&g_cursor[c], 1);
        g_src[pos] = row[e];
    }
}

// ---------------- pass 1: h = relu(agg(h0) + b1), emitted as bf16 split ----------------
__global__ void aggregate_relu_split_kernel(const float* __restrict__ H,
                                            const float* __restrict__ bias,
                                            __nv_bfloat16* __restrict__ outs) {
    int node = blockIdx.x;
    int f = threadIdx.x * 4;
    float di = g_dinv[node];
    int s0 = g_off[node], s1 = g_off[node + 1];
    float4 acc = make_float4(0.f, 0.f, 0.f, 0.f);
    for (int e = s0; e < s1; e++) {
        int s = g_src[e];
        float w = g_dinv[s];
        float4 v = *(const float4*)&H[(size_t)s * HID + f];
        acc.x += w * v.x; acc.y += w * v.y; acc.z += w * v.z; acc.w += w * v.w;
    }
    float4 hv = *(const float4*)&H[(size_t)node * HID + f];
    float4 b = *(const float4*)&bias[f];
    float r[4];
    r[0] = fmaxf(di * acc.x + di * di * hv.x + b.x, 0.f);
    r[1] = fmaxf(di * acc.y + di * di * hv.y + b.y, 0.f);
    r[2] = fmaxf(di * acc.z + di * di * hv.z + b.z, 0.f);
    r[3] = fmaxf(di * acc.w + di * di * hv.w + b.w, 0.f);
    size_t rb = (size_t)node * 1024 + f;
    #pragma unroll
    for (int j = 0; j < 4; j++) {
        __nv_bfloat16 hi, lo;
        split2(r[j], hi, lo);
        outs[rb + j] = hi;
        outs[rb + 512 + j] = lo;
    }
}

// ---------------- pass 2: final 256-wide aggregation of hw -> mu/z/lv/zs ----------------
__global__ void final_agg_kernel(const float* __restrict__ HW,
                                 const float* __restrict__ bmu, const float* __restrict__ blv,
                                 float* __restrict__ mu, float* __restrict__ z,
                                 float* __restrict__ lv, __nv_bfloat16* __restrict__ zs) {
    int node = blockIdx.x;
    int f = threadIdx.x * 4;                 // 64 threads * 4 = 256
    float di = g_dinv[node];
    int s0 = g_off[node], s1 = g_off[node + 1];
    float4 acc = make_float4(0.f, 0.f, 0.f, 0.f);
    for (int e = s0; e < s1; e++) {
        int s = g_src[e];
        float w = g_dinv[s];
        float4 v = *(const float4*)&HW[(size_t)s * 256 + f];
        acc.x += w * v.x; acc.y += w * v.y; acc.z += w * v.z; acc.w += w * v.w;
    }
    float4 hv = *(const float4*)&HW[(size_t)node * 256 + f];
    float4 r;
    r.x = di * acc.x + di * di * hv.x;
    r.y = di * acc.y + di * di * hv.y;
    r.z = di * acc.z + di * di * hv.z;
    r.w = di * acc.w + di * di * hv.w;
    if (f < 128) {
        float4 b = *(const float4*)&bmu[f];
        r.x += b.x; r.y += b.y; r.z += b.z; r.w += b.w;
        size_t o = (size_t)node * LAT + f;
        *(float4*)&mu[o] = r;
        *(float4*)&z[o] = r;
        __nv_bfloat162 p0, p1;
        p0.x = __float2bfloat16(r.x); p0.y = __float2bfloat16(r.y);
        p1.x = __float2bfloat16(r.z); p1.y = __float2bfloat16(r.w);
        *(__nv_bfloat162*)&zs[o] = p0;
        *(__nv_bfloat162*)&zs[o + 2] = p1;
    } else {
        float4 b = *(const float4*)&blv[f - 128];
        r.x += b.x; r.y += b.y; r.z += b.z; r.w += b.w;
        *(float4*)&lv[(size_t)node * LAT + f - 128] = r;
    }
}

// ---------------- MMA primitives ----------------
__device__ __forceinline__ void ldsm_x4(uint32_t& r0, uint32_t& r1, uint32_t& r2, uint32_t& r3,
                                        uint32_t addr) {
    asm volatile("ldmatrix.sync.aligned.m8n8.x4.shared.b16 {%0,%1,%2,%3}, [%4];"
                 : "=r"(r0), "=r"(r1), "=r"(r2), "=r"(r3) : "r"(addr));
}

__device__ __forceinline__ void mma_bf16(float* c, const uint32_t* a, const uint32_t* b) {
    asm volatile(
        "mma.sync.aligned.m16n8k16.row.col.f32.bf16.bf16.f32 "
        "{%0,%1,%2,%3}, {%4,%5,%6,%7}, {%8,%9}, {%0,%1,%2,%3};"
        : "+f"(c[0]), "+f"(c[1]), "+f"(c[2]), "+f"(c[3])
        : "r"(a[0]), "r"(a[1]), "r"(a[2]), "r"(a[3]), "r"(b[0]), "r"(b[1]));
}

__device__ __forceinline__ void cp_async16(uint32_t dst, const void* src) {
    asm volatile("cp.async.cg.shared.global [%0], [%1], 16;" :: "r"(dst), "l"(src));
}

// ---------------- gemm1: h0 = x @ W1^T-split, A read as fp32 + in-register split ----------------
__global__ __launch_bounds__(256) void mma_gemm_xf32(
    const float* __restrict__ X, const __nv_bfloat16* __restrict__ B,
    float* __restrict__ C0) {
    constexpr int KPART = 512;
    constexpr int CPK = KPART / 64;          // 8
    constexpr int NSTEP = 3 * CPK;           // 24

    __shared__ __nv_bfloat16 As[128 * 64];
    __shared__ __nv_bfloat16 Bs[128 * 64];
    int tid = threadIdx.x;
    int wid = tid >> 5;
    int lane = tid & 31;
    int wm = wid & 3;
    int wn = wid >> 2;

    const float* Abase = X + (size_t)(blockIdx.y * 128) * KPART;
    const __nv_bfloat16* Bbase = B + (size_t)(blockIdx.x * 128) * (2 * KPART);
    uint32_t as_u = smem_to_u32(As);
    uint32_t bs_u = smem_to_u32(Bs);

    float acc[2][8][4] = {};

    for (int step = 0; step < NSTEP; step++) {
        int p = step / CPK;
        int kk = step % CPK;
        int alo = (p == 2);
        int boff = (p == 1) ? KPART : 0;
        #pragma unroll
        for (int i = 0; i < 4; i++) {
            int cid = tid + i * 256;
            int row = cid >> 3;
            int ch = cid & 7;
            int sw = (ch ^ (row & 7)) * 8;
            const float* src = Abase + (size_t)row * KPART + kk * 64 + ch * 8;
            float4 v0 = *(const float4*)src;
            float4 v1 = *(const float4*)(src + 4);
            float vs[8] = {v0.x, v0.y, v0.z, v0.w, v1.x, v1.y, v1.z, v1.w};
            __nv_bfloat16 b8[8];
            #pragma unroll
            for (int j = 0; j < 8; j++) {
                __nv_bfloat16 hi = __float2bfloat16(vs[j]);
                b8[j] = alo ? __float2bfloat16(vs[j] - __bfloat162float(hi)) : hi;
            }
            *(float4*)&As[row * 64 + sw] = *(float4*)b8;
            *(float4*)&Bs[row * 64 + sw] =
                *(const float4*)&Bbase[(size_t)row * (2 * KPART) + boff + kk * 64 + ch * 8];
        }
        __syncthreads();

        #pragma unroll
        for (int ks = 0; ks < 4; ks++) {
            uint32_t a[2][4];
            #pragma unroll
            for (int mt = 0; mt < 2; mt++) {
                int row = wm * 32 + mt * 16 + (lane & 15);
                int ch = ks * 2 + (lane >> 4);
                uint32_t addr = as_u + row * 128 + ((ch ^ (row & 7)) << 4);
                ldsm_x4(a[mt][0], a[mt][1], a[mt][2], a[mt][3], addr);
            }
            uint32_t b[8][2];
            #pragma unroll
            for (int q = 0; q < 4; q++) {
                int grp = lane >> 3;
                int nrow = wn * 64 + q * 16 + ((grp >> 1) << 3) + (lane & 7);
                int ch = ks * 2 + (grp & 1);
                uint32_t addr = bs_u + nrow * 128 + ((ch ^ (nrow & 7)) << 4);
                ldsm_x4(b[q * 2][0], b[q * 2][1], b[q * 2 + 1][0], b[q * 2 + 1][1], addr);
            }
            #pragma unroll
            for (int mt = 0; mt < 2; mt++)
                #pragma unroll
                for (int nt = 0; nt < 8; nt++)
                    mma_bf16(acc[mt][nt], a[mt], b[nt]);
        }
        __syncthreads();
    }

    int rbase = blockIdx.y * 128 + wm * 32 + (lane >> 2);
    int cloc = wn * 64 + (lane & 3) * 2;
    #pragma unroll
    for (int mt = 0; mt < 2; mt++) {
        #pragma unroll
        for (int nt = 0; nt < 8; nt++) {
            float* c = acc[mt][nt];
            int gc = blockIdx.x * 128 + cloc + nt * 8;
            #pragma unroll
            for (int rr = 0; rr < 2; rr++) {
                size_t row = (size_t)(rbase + mt * 16 + rr * 8);
                *(float2*)&C0[row * 512 + gc] = make_float2(c[rr * 2 + 0], c[rr * 2 + 1]);
            }
        }
    }
}

// ---------------- gemm2 (pipelined): C = A @ B^T, cp.async 2-stage double buffer ----------------
// 128 CTAs <= 148 SMs: occupancy irrelevant, intra-CTA pipelining is pure upside.
// dynamic SMEM: 2 stages x (A 16KB + B 16KB) = 64KB.
template<int KPART, int PHASES>
__global__ __launch_bounds__(256) void mma_gemm_pipe(
    const __nv_bfloat16* __restrict__ A, const __nv_bfloat16* __restrict__ B,
    float* __restrict__ C0, int ldc) {
    constexpr int RS = (PHASES == 3 ? 2 : 1) * KPART;
    constexpr int CPK = KPART / 64;
    constexpr int NSTEP = PHASES * CPK;

    extern __shared__ __nv_bfloat16 sm[];
    int tid = threadIdx.x;
    int wid = tid >> 5;
    int lane = tid & 31;
    int wm = wid & 3;
    int wn = wid >> 2;

    const __nv_bfloat16* Abase = A + (size_t)(blockIdx.y * 128) * RS;
    const __nv_bfloat16* Bbase = B + (size_t)(blockIdx.x * 128) * RS;
    uint32_t smb = smem_to_u32(sm);

    auto issue = [&](int s, int step) {
        int p = step / CPK;
        int kk = step % CPK;
        int aoff = (PHASES == 3 && p == 2) ? KPART : 0;
        int boff = (PHASES == 3 && p == 1) ? KPART : 0;
        uint32_t asu = smb + (uint32_t)s * 32768u;
        uint32_t bsu = asu + 16384u;
        #pragma unroll
        for (int i = 0; i < 4; i++) {
            int cid = tid + i * 256;
            int row = cid >> 3;
            int ch = cid & 7;
            uint32_t sw = (uint32_t)((ch ^ (row & 7)) << 4);
            cp_async16(asu + row * 128 + sw,
                       Abase + (size_t)row * RS + aoff + kk * 64 + ch * 8);
            cp_async16(bsu + row * 128 + sw,
                       Bbase + (size_t)row * RS + boff + kk * 64 + ch * 8);
        }
    };

    float acc[2][8][4] = {};

    issue(0, 0);
    asm volatile("cp.async.commit_group;");
    for (int step = 0; step < NSTEP; step++) {
        int s = step & 1;
        if (step + 1 < NSTEP) issue(s ^ 1, step + 1);
        asm volatile("cp.async.commit_group;");
        asm volatile("cp.async.wait_group 1;");
        __syncthreads();

        uint32_t as_u = smb + (uint32_t)s * 32768u;
        uint32_t bs_u = as_u + 16384u;
        #pragma unroll
        for (int ks = 0; ks < 4; ks++) {
            uint32_t a[2][4];
            #pragma unroll
            for (int mt = 0; mt < 2; mt++) {
                int row = wm * 32 + mt * 16 + (lane & 15);
                int ch = ks * 2 + (lane >> 4);
                uint32_t addr = as_u + row * 128 + ((ch ^ (row & 7)) << 4);
                ldsm_x4(a[mt][0], a[mt][1], a[mt][2], a[mt][3], addr);
            }
            uint32_t b[8][2];
            #pragma unroll
            for (int q = 0; q < 4; q++) {
                int grp = lane >> 3;
                int nrow = wn * 64 + q * 16 + ((grp >> 1) << 3) + (lane & 7);
                int ch = ks * 2 + (grp & 1);
                uint32_t addr = bs_u + nrow * 128 + ((ch ^ (nrow & 7)) << 4);
                ldsm_x4(b[q * 2][0], b[q * 2][1], b[q * 2 + 1][0], b[q * 2 + 1][1], addr);
            }
            #pragma unroll
            for (int mt = 0; mt < 2; mt++)
                #pragma unroll
                for (int nt = 0; nt < 8; nt++)
                    mma_bf16(acc[mt][nt], a[mt], b[nt]);
        }
        __syncthreads();
    }

    int rbase = blockIdx.y * 128 + wm * 32 + (lane >> 2);
    int cloc = wn * 64 + (lane & 3) * 2;
    #pragma unroll
    for (int mt = 0; mt < 2; mt++) {
        #pragma unroll
        for (int nt = 0; nt < 8; nt++) {
            float* c = acc[mt][nt];
            int gc = blockIdx.x * 128 + cloc + nt * 8;
            #pragma unroll
            for (int rr = 0; rr < 2; rr++) {
                size_t row = (size_t)(rbase + mt * 16 + rr * 8);
                *(float2*)&C0[row * ldc + gc] = make_float2(c[rr * 2 + 0], c[rr * 2 + 1]);
            }
        }
    }
}

// ---------------- dense zzt (R13 version): A_pred = sigmoid(Z @ Z^T) ----------------
__global__ __launch_bounds__(256) void zzt_mma_kernel(const __nv_bfloat16* __restrict__ Zs,
                                                      float* __restrict__ out) {
    __shared__ __nv_bfloat16 As[128 * 64];
    __shared__ __nv_bfloat16 Bs[128 * 64];
    int tid = threadIdx.x;
    int wid = tid >> 5;
    int lane = tid & 31;
    int wm = wid & 3;
    int wn = wid >> 2;

    const __nv_bfloat16* Abase = Zs + (size_t)(blockIdx.y * 128) * 128;
    const __nv_bfloat16* Bbase = Zs + (size_t)(blockIdx.x * 128) * 128;
    uint32_t as_u = smem_to_u32(As);
    uint32_t bs_u = smem_to_u32(Bs);

    float acc[2][8][4] = {};

    for (int kk = 0; kk < 2; kk++) {
        #pragma unroll
        for (int i = 0; i < 4; i++) {
            int cid = tid + i * 256;
            int row = cid >> 3;
            int ch = cid & 7;
            int sw = (ch ^ (row & 7)) * 8;
            *(float4*)&As[row * 64 + sw] =
                *(const float4*)&Abase[(size_t)row * 128 + kk * 64 + ch * 8];
            *(float4*)&Bs[row * 64 + sw] =
                *(const float4*)&Bbase[(size_t)row * 128 + kk * 64 + ch * 8];
        }
        __syncthreads();

        #pragma unroll
        for (int ks = 0; ks < 4; ks++) {
            uint32_t a[2][4];
            #pragma unroll
            for (int mt = 0; mt < 2; mt++) {
                int row = wm * 32 + mt * 16 + (lane & 15);
                int ch = ks * 2 + (lane >> 4);
                uint32_t addr = as_u + row * 128 + ((ch ^ (row & 7)) << 4);
                ldsm_x4(a[mt][0], a[mt][1], a[mt][2], a[mt][3], addr);
            }
            uint32_t bfr[8][2];
            #pragma unroll
            for (int q = 0; q < 4; q++) {
                int grp = lane >> 3;
                int nrow = wn * 64 + q * 16 + ((grp >> 1) << 3) + (lane & 7);
                int ch = ks * 2 + (grp & 1);
                uint32_t addr = bs_u + nrow * 128 + ((ch ^ (nrow & 7)) << 4);
                ldsm_x4(bfr[q * 2][0], bfr[q * 2][1], bfr[q * 2 + 1][0], bfr[q * 2 + 1][1], addr);
            }
            #pragma unroll
            for (int mt = 0; mt < 2; mt++)
                #pragma unroll
                for (int nt = 0; nt < 8; nt++)
                    mma_bf16(acc[mt][nt], a[mt], bfr[nt]);
        }
        __syncthreads();
    }

    int rbase = blockIdx.y * 128 + wm * 32 + (lane >> 2);
    int cbase = blockIdx.x * 128 + wn * 64 + (lane & 3) * 2;
    #pragma unroll
    for (int mt = 0; mt < 2; mt++) {
        #pragma unroll
        for (int nt = 0; nt < 8; nt++) {
            float* c = acc[mt][nt];
            size_t r0 = (size_t)(rbase + mt * 16);
            size_t c0 = (size_t)(cbase + nt * 8);
            float2 v0, v1;
            v0.x = 1.f / (1.f + __expf(-c[0]));
            v0.y = 1.f / (1.f + __expf(-c[1]));
            v1.x = 1.f / (1.f + __expf(-c[2]));
            v1.y = 1.f / (1.f + __expf(-c[3]));
            *(float2*)&out[r0 * NN + c0] = v0;
            *(float2*)&out[(r0 + 8) * NN + c0] = v1;
        }
    }
}

// ---------------- aux stream/events (created once, on the non-captured first call) ----------------
struct Aux {
    cudaStream_t s2;
    cudaEvent_t  e_fork, e_join;
    Aux() {
        cudaStreamCreateWithFlags(&s2, cudaStreamNonBlocking);
        cudaEventCreateWithFlags(&e_fork, cudaEventDisableTiming);
        cudaEventCreateWithFlags(&e_join, cudaEventDisableTiming);
        cudaFuncSetAttribute((const void*)mma_gemm_pipe<512, 3>,
                             cudaFuncAttributeMaxDynamicSharedMemorySize, 65536);
    }
};
static Aux& aux() { static Aux a; return a; }

// ---------------- launch ----------------
extern "C" void kernel_launch(void* const* d_in, const int* in_sizes, int n_in,
                              void* d_out, int out_size) {
    const int*   edge = (const int*)d_in[0];
    const float* x    = (const float*)d_in[1];
    const float* W1   = (const float*)d_in[2];
    const float* b1   = (const float*)d_in[3];
    const float* Wmu  = (const float*)d_in[4];
    const float* bmu  = (const float*)d_in[5];
    const float* Wlv  = (const float*)d_in[6];
    const float* blv  = (const float*)d_in[7];

    const int* row = edge;
    const int* col = edge + EE;

    float* out     = (float*)d_out;
    float* A_pred  = out;
    float* mu_out  = out + (size_t)NN * NN;
    float* lv_out  = mu_out + (size_t)NN * LAT;
    float* z_out   = lv_out + (size_t)NN * LAT;

    float* h0;   cudaGetSymbolAddress((void**)&h0,   g_h0);
    float* hw;   cudaGetSymbolAddress((void**)&hw,   g_hw);
    __nv_bfloat16* zs;   cudaGetSymbolAddress((void**)&zs,   g_zs);
    __nv_bfloat16* hs;   cudaGetSymbolAddress((void**)&hs,   g_hs);
    __nv_bfloat16* w1s;  cudaGetSymbolAddress((void**)&w1s,  g_w1s);
    __nv_bfloat16* wmls; cudaGetSymbolAddress((void**)&wmls, g_wmls);

    Aux& a = aux();

    // fork: aux stream runs graph preproc in parallel with wsplit+gemm1
    cudaEventRecord(a.e_fork, 0);
    cudaStreamWaitEvent(a.s2, a.e_fork, 0);
    zero_kernel<<<(NN + 255) / 256, 256, 0, a.s2>>>();
    count_kernel<<<(EE + 255) / 256, 256, 0, a.s2>>>(col);
    scan_kernel<<<1, 1024, 0, a.s2>>>();
    fill_kernel<<<(EE + 255) / 256, 256, 0, a.s2>>>(row, col);
    cudaEventRecord(a.e_join, a.s2);

    // main stream: weight splits (tiny), then layer-1 GEMM reading x fp32 directly
    wsplit_kernel<<<(512 * 512) / 256, 256>>>(W1, Wmu, Wlv, w1s, wmls);
    mma_gemm_xf32<<<dim3(4, 64), 256>>>(x, w1s, h0);

    // join: aggregation needs CSR (aux) + h0 (main)
    cudaStreamWaitEvent(0, a.e_join, 0);
    aggregate_relu_split_kernel<<<NN, 128>>>(h0, b1, hs);

    // layer 2: pipelined gemm2 (128 CTAs -> every CTA owns an SM), then aggregate
    mma_gemm_pipe<512, 3><<<dim3(2, 64), 256, 65536>>>(hs, wmls, hw, 256);
    final_agg_kernel<<<NN, 64>>>(hw, bmu, blv, mu_out, z_out, lv_out, zs);

    // decode: A_pred = sigmoid(z z^T), dense
    zzt_mma_kernel<<<dim3(64, 64), 256>>>(zs, A_pred);
}

// round 17
// speedup vs baseline: 1.0936x; 1.0662x over previous
#include <cuda_runtime.h>
#include <cuda_bf16.h>
#include <math.h>
#include <cstdint>

#define NN   8192
#define EE   262144
#define HID  512
#define LAT  128

// ---------------- scratch (__device__ globals; no allocation) ----------------
__device__ float g_h0[NN * HID];                 // x @ W1
__device__ float g_hw[NN * 256];                 // h @ [Wmu|Wlv]  (pre-aggregation)
__device__ float g_dinv[NN];
__device__ int   g_deg[NN];
__device__ int   g_off[NN + 1];
__device__ int   g_cursor[NN];
__device__ int   g_src[EE];
__device__ __nv_bfloat16 g_zs[NN * 128];         // z hi-only bf16
__device__ __nv_bfloat16 g_xs[NN * 1024];        // x split: [:,0:512]=hi, [:,512:1024]=lo
__device__ __nv_bfloat16 g_hs[NN * 1024];        // h split (relu(agg(h0)+b1))
__device__ __nv_bfloat16 g_w1s[512 * 1024];      // W1^T split: [n][k-hi | k-lo]
__device__ __nv_bfloat16 g_wmls[256 * 1024];     // [Wmu^T ; Wlv^T] split

__device__ __forceinline__ uint32_t smem_to_u32(const void* smem_ptr) {
    uint32_t addr;
    asm("{ .reg .u64 tmp; cvta.to.shared.u64 tmp, %1; cvt.u32.u64 %0, tmp; }"
        : "=r"(addr) : "l"(smem_ptr));
    return addr;
}

__device__ __forceinline__ void split2(float v, __nv_bfloat16& hi, __nv_bfloat16& lo) {
    hi = __float2bfloat16(v);
    lo = __float2bfloat16(v - __bfloat162float(hi));
}

// ---------------- prep: split x + W1/Wmu/Wlv (R10-validated combined kernel) ----------------
__global__ void prep_kernel(const float* __restrict__ x, const float* __restrict__ W1,
                            const float* __restrict__ Wmu, const float* __restrict__ Wlv,
                            __nv_bfloat16* __restrict__ xs, __nv_bfloat16* __restrict__ w1s,
                            __nv_bfloat16* __restrict__ wmls) {
    int i = blockIdx.x * blockDim.x + threadIdx.x;   // 0 .. NN*512-1
    {
        int row = i >> 9, k = i & 511;
        __nv_bfloat16 hi, lo;
        split2(x[i], hi, lo);
        xs[(size_t)row * 1024 + k] = hi;
        xs[(size_t)row * 1024 + 512 + k] = lo;
    }
    if (i < 512 * 512) {
        int k = i >> 9, n = i & 511;
        __nv_bfloat16 hi, lo;
        split2(W1[i], hi, lo);
        w1s[(size_t)n * 1024 + k] = hi;
        w1s[(size_t)n * 1024 + 512 + k] = lo;
    }
    if (i < 512 * 128) {
        int k = i >> 7, n = i & 127;
        __nv_bfloat16 hi, lo;
        split2(Wmu[i], hi, lo);
        wmls[(size_t)n * 1024 + k] = hi;
        wmls[(size_t)n * 1024 + 512 + k] = lo;
        split2(Wlv[i], hi, lo);
        wmls[(size_t)(n + 128) * 1024 + k] = hi;
        wmls[(size_t)(n + 128) * 1024 + 512 + k] = lo;
    }
}

// ---------------- graph preprocessing (aux-stream chain) ----------------
__global__ void zero_kernel() {
    int i = blockIdx.x * blockDim.x + threadIdx.x;
    if (i < NN) { g_deg[i] = 0; g_cursor[i] = 0; }
}

__global__ void count_kernel(const int* __restrict__ col) {
    int e = blockIdx.x * blockDim.x + threadIdx.x;
    if (e < EE) atomicAdd(&g_deg[col[e]], 1);
}

__global__ void scan_kernel() {
    __shared__ int wtot[32];
    int t = threadIdx.x, lane = t & 31, w = t >> 5;
    int base = t * 8;
    int d[8], pre[8];
    int sum = 0;
    #pragma unroll
    for (int i = 0; i < 8; i++) { d[i] = g_deg[base + i]; pre[i] = sum; sum += d[i]; }
    int v = sum;
    #pragma unroll
    for (int off = 1; off < 32; off <<= 1) {
        int n = __shfl_up_sync(0xffffffffu, v, off);
        if (lane >= off) v += n;
    }
    if (lane == 31) wtot[w] = v;
    __syncthreads();
    if (w == 0) {
        int x = wtot[lane];
        int y = x;
        #pragma unroll
        for (int off = 1; off < 32; off <<= 1) {
            int n = __shfl_up_sync(0xffffffffu, y, off);
            if (lane >= off) y += n;
        }
        wtot[lane] = y - x;
    }
    __syncthreads();
    int excl = v - sum + wtot[w];
    #pragma unroll
    for (int i = 0; i < 8; i++) g_off[base + i] = excl + pre[i];
    #pragma unroll
    for (int i = 0; i < 8; i++) g_dinv[base + i] = rsqrtf((float)(d[i] + 1));
    if (t == 1023) g_off[NN] = excl + sum;
}

__global__ void fill_kernel(const int* __restrict__ row, const int* __restrict__ col) {
    int e = blockIdx.x * blockDim.x + threadIdx.x;
    if (e < EE) {
        int c = col[e];
        int pos = g_off[c] + atomicAdd(&g_cursor[c], 1);
        g_src[pos] = row[e];
    }
}

// ---------------- pass 1: h = relu(agg(h0) + b1), emitted as bf16 split ----------------
__global__ void aggregate_relu_split_kernel(const float* __restrict__ H,
                                            const float* __restrict__ bias,
                                            __nv_bfloat16* __restrict__ outs) {
    int node = blockIdx.x;
    int f = threadIdx.x * 4;
    float di = g_dinv[node];
    int s0 = g_off[node], s1 = g_off[node + 1];
    float4 acc = make_float4(0.f, 0.f, 0.f, 0.f);
    for (int e = s0; e < s1; e++) {
        int s = g_src[e];
        float w = g_dinv[s];
        float4 v = *(const float4*)&H[(size_t)s * HID + f];
        acc.x += w * v.x; acc.y += w * v.y; acc.z += w * v.z; acc.w += w * v.w;
    }
    float4 hv = *(const float4*)&H[(size_t)node * HID + f];
    float4 b = *(const float4*)&bias[f];
    float r[4];
    r[0] = fmaxf(di * acc.x + di * di * hv.x + b.x, 0.f);
    r[1] = fmaxf(di * acc.y + di * di * hv.y + b.y, 0.f);
    r[2] = fmaxf(di * acc.z + di * di * hv.z + b.z, 0.f);
    r[3] = fmaxf(di * acc.w + di * di * hv.w + b.w, 0.f);
    size_t rb = (size_t)node * 1024 + f;
    #pragma unroll
    for (int j = 0; j < 4; j++) {
        __nv_bfloat16 hi, lo;
        split2(r[j], hi, lo);
        outs[rb + j] = hi;
        outs[rb + 512 + j] = lo;
    }
}

// ---------------- pass 2: final 256-wide aggregation of hw -> mu/z/lv/zs ----------------
__global__ void final_agg_kernel(const float* __restrict__ HW,
                                 const float* __restrict__ bmu, const float* __restrict__ blv,
                                 float* __restrict__ mu, float* __restrict__ z,
                                 float* __restrict__ lv, __nv_bfloat16* __restrict__ zs) {
    int node = blockIdx.x;
    int f = threadIdx.x * 4;                 // 64 threads * 4 = 256
    float di = g_dinv[node];
    int s0 = g_off[node], s1 = g_off[node + 1];
    float4 acc = make_float4(0.f, 0.f, 0.f, 0.f);
    for (int e = s0; e < s1; e++) {
        int s = g_src[e];
        float w = g_dinv[s];
        float4 v = *(const float4*)&HW[(size_t)s * 256 + f];
        acc.x += w * v.x; acc.y += w * v.y; acc.z += w * v.z; acc.w += w * v.w;
    }
    float4 hv = *(const float4*)&HW[(size_t)node * 256 + f];
    float4 r;
    r.x = di * acc.x + di * di * hv.x;
    r.y = di * acc.y + di * di * hv.y;
    r.z = di * acc.z + di * di * hv.z;
    r.w = di * acc.w + di * di * hv.w;
    if (f < 128) {
        float4 b = *(const float4*)&bmu[f];
        r.x += b.x; r.y += b.y; r.z += b.z; r.w += b.w;
        size_t o = (size_t)node * LAT + f;
        *(float4*)&mu[o] = r;
        *(float4*)&z[o] = r;
        __nv_bfloat162 p0, p1;
        p0.x = __float2bfloat16(r.x); p0.y = __float2bfloat16(r.y);
        p1.x = __float2bfloat16(r.z); p1.y = __float2bfloat16(r.w);
        *(__nv_bfloat162*)&zs[o] = p0;
        *(__nv_bfloat162*)&zs[o + 2] = p1;
    } else {
        float4 b = *(const float4*)&blv[f - 128];
        r.x += b.x; r.y += b.y; r.z += b.z; r.w += b.w;
        *(float4*)&lv[(size_t)node * LAT + f - 128] = r;
    }
}

// ---------------- MMA primitives ----------------
__device__ __forceinline__ void ldsm_x4(uint32_t& r0, uint32_t& r1, uint32_t& r2, uint32_t& r3,
                                        uint32_t addr) {
    asm volatile("ldmatrix.sync.aligned.m8n8.x4.shared.b16 {%0,%1,%2,%3}, [%4];"
                 : "=r"(r0), "=r"(r1), "=r"(r2), "=r"(r3) : "r"(addr));
}

__device__ __forceinline__ void mma_bf16(float* c, const uint32_t* a, const uint32_t* b) {
    asm volatile(
        "mma.sync.aligned.m16n8k16.row.col.f32.bf16.bf16.f32 "
        "{%0,%1,%2,%3}, {%4,%5,%6,%7}, {%8,%9}, {%0,%1,%2,%3};"
        : "+f"(c[0]), "+f"(c[1]), "+f"(c[2]), "+f"(c[3])
        : "r"(a[0]), "r"(a[1]), "r"(a[2]), "r"(a[3]), "r"(b[0]), "r"(b[1]));
}

__device__ __forceinline__ void cp_async16(uint32_t dst, const void* src) {
    asm volatile("cp.async.cg.shared.global [%0], [%1], 16;" :: "r"(dst), "l"(src));
}

// ---------------- pipelined GEMM: C = A @ B^T, cp.async 2-stage double buffer ----------------
// __launch_bounds__(256, 2): regs <= 128 so occ 2 is guaranteed (2 x 64KB smem fits 228KB).
// Intra-CTA pipelining + inter-CTA overlap; single wave for both gemm1 (256 CTAs) and gemm2 (128).
template<int KPART, int PHASES>
__global__ __launch_bounds__(256, 2) void mma_gemm_pipe(
    const __nv_bfloat16* __restrict__ A, const __nv_bfloat16* __restrict__ B,
    float* __restrict__ C0, int ldc) {
    constexpr int RS = (PHASES == 3 ? 2 : 1) * KPART;
    constexpr int CPK = KPART / 64;
    constexpr int NSTEP = PHASES * CPK;

    extern __shared__ __nv_bfloat16 sm[];
    int tid = threadIdx.x;
    int wid = tid >> 5;
    int lane = tid & 31;
    int wm = wid & 3;
    int wn = wid >> 2;

    const __nv_bfloat16* Abase = A + (size_t)(blockIdx.y * 128) * RS;
    const __nv_bfloat16* Bbase = B + (size_t)(blockIdx.x * 128) * RS;
    uint32_t smb = smem_to_u32(sm);

    auto issue = [&](int s, int step) {
        int p = step / CPK;
        int kk = step % CPK;
        int aoff = (PHASES == 3 && p == 2) ? KPART : 0;
        int boff = (PHASES == 3 && p == 1) ? KPART : 0;
        uint32_t asu = smb + (uint32_t)s * 32768u;
        uint32_t bsu = asu + 16384u;
        #pragma unroll
        for (int i = 0; i < 4; i++) {
            int cid = tid + i * 256;
            int row = cid >> 3;
            int ch = cid & 7;
            uint32_t sw = (uint32_t)((ch ^ (row & 7)) << 4);
            cp_async16(asu + row * 128 + sw,
                       Abase + (size_t)row * RS + aoff + kk * 64 + ch * 8);
            cp_async16(bsu + row * 128 + sw,
                       Bbase + (size_t)row * RS + boff + kk * 64 + ch * 8);
        }
    };

    float acc[2][8][4] = {};

    issue(0, 0);
    asm volatile("cp.async.commit_group;");
    for (int step = 0; step < NSTEP; step++) {
        int s = step & 1;
        if (step + 1 < NSTEP) issue(s ^ 1, step + 1);
        asm volatile("cp.async.commit_group;");
        asm volatile("cp.async.wait_group 1;");
        __syncthreads();

        uint32_t as_u = smb + (uint32_t)s * 32768u;
        uint32_t bs_u = as_u + 16384u;
        #pragma unroll
        for (int ks = 0; ks < 4; ks++) {
            uint32_t a[2][4];
            #pragma unroll
            for (int mt = 0; mt < 2; mt++) {
                int row = wm * 32 + mt * 16 + (lane & 15);
                int ch = ks * 2 + (lane >> 4);
                uint32_t addr = as_u + row * 128 + ((ch ^ (row & 7)) << 4);
                ldsm_x4(a[mt][0], a[mt][1], a[mt][2], a[mt][3], addr);
            }
            uint32_t b[8][2];
            #pragma unroll
            for (int q = 0; q < 4; q++) {
                int grp = lane >> 3;
                int nrow = wn * 64 + q * 16 + ((grp >> 1) << 3) + (lane & 7);
                int ch = ks * 2 + (grp & 1);
                uint32_t addr = bs_u + nrow * 128 + ((ch ^ (nrow & 7)) << 4);
                ldsm_x4(b[q * 2][0], b[q * 2][1], b[q * 2 + 1][0], b[q * 2 + 1][1], addr);
            }
            #pragma unroll
            for (int mt = 0; mt < 2; mt++)
                #pragma unroll
                for (int nt = 0; nt < 8; nt++)
                    mma_bf16(acc[mt][nt], a[mt], b[nt]);
        }
        __syncthreads();
    }

    int rbase = blockIdx.y * 128 + wm * 32 + (lane >> 2);
    int cloc = wn * 64 + (lane & 3) * 2;
    #pragma unroll
    for (int mt = 0; mt < 2; mt++) {
        #pragma unroll
        for (int nt = 0; nt < 8; nt++) {
            float* c = acc[mt][nt];
            int gc = blockIdx.x * 128 + cloc + nt * 8;
            #pragma unroll
            for (int rr = 0; rr < 2; rr++) {
                size_t row = (size_t)(rbase + mt * 16 + rr * 8);
                *(float2*)&C0[row * ldc + gc] = make_float2(c[rr * 2 + 0], c[rr * 2 + 1]);
            }
        }
    }
}

// ---------------- dense zzt: A_pred = sigmoid(Z @ Z^T) ----------------
__global__ __launch_bounds__(256) void zzt_mma_kernel(const __nv_bfloat16* __restrict__ Zs,
                                                      float* __restrict__ out) {
    __shared__ __nv_bfloat16 As[128 * 64];
    __shared__ __nv_bfloat16 Bs[128 * 64];
    int tid = threadIdx.x;
    int wid = tid >> 5;
    int lane = tid & 31;
    int wm = wid & 3;
    int wn = wid >> 2;

    const __nv_bfloat16* Abase = Zs + (size_t)(blockIdx.y * 128) * 128;
    const __nv_bfloat16* Bbase = Zs + (size_t)(blockIdx.x * 128) * 128;
    uint32_t as_u = smem_to_u32(As);
    uint32_t bs_u = smem_to_u32(Bs);

    float acc[2][8][4] = {};

    for (int kk = 0; kk < 2; kk++) {
        #pragma unroll
        for (int i = 0; i < 4; i++) {
            int cid = tid + i * 256;
            int row = cid >> 3;
            int ch = cid & 7;
            int sw = (ch ^ (row & 7)) * 8;
            *(float4*)&As[row * 64 + sw] =
                *(const float4*)&Abase[(size_t)row * 128 + kk * 64 + ch * 8];
            *(float4*)&Bs[row * 64 + sw] =
                *(const float4*)&Bbase[(size_t)row * 128 + kk * 64 + ch * 8];
        }
        __syncthreads();

        #pragma unroll
        for (int ks = 0; ks < 4; ks++) {
            uint32_t a[2][4];
            #pragma unroll
            for (int mt = 0; mt < 2; mt++) {
                int row = wm * 32 + mt * 16 + (lane & 15);
                int ch = ks * 2 + (lane >> 4);
                uint32_t addr = as_u + row * 128 + ((ch ^ (row & 7)) << 4);
                ldsm_x4(a[mt][0], a[mt][1], a[mt][2], a[mt][3], addr);
            }
            uint32_t bfr[8][2];
            #pragma unroll
            for (int q = 0; q < 4; q++) {
                int grp = lane >> 3;
                int nrow = wn * 64 + q * 16 + ((grp >> 1) << 3) + (lane & 7);
                int ch = ks * 2 + (grp & 1);
                uint32_t addr = bs_u + nrow * 128 + ((ch ^ (nrow & 7)) << 4);
                ldsm_x4(bfr[q * 2][0], bfr[q * 2][1], bfr[q * 2 + 1][0], bfr[q * 2 + 1][1], addr);
            }
            #pragma unroll
            for (int mt = 0; mt < 2; mt++)
                #pragma unroll
                for (int nt = 0; nt < 8; nt++)
                    mma_bf16(acc[mt][nt], a[mt], bfr[nt]);
        }
        __syncthreads();
    }

    int rbase = blockIdx.y * 128 + wm * 32 + (lane >> 2);
    int cbase = blockIdx.x * 128 + wn * 64 + (lane & 3) * 2;
    #pragma unroll
    for (int mt = 0; mt < 2; mt++) {
        #pragma unroll
        for (int nt = 0; nt < 8; nt++) {
            float* c = acc[mt][nt];
            size_t r0 = (size_t)(rbase + mt * 16);
            size_t c0 = (size_t)(cbase + nt * 8);
            float2 v0, v1;
            v0.x = 1.f / (1.f + __expf(-c[0]));
            v0.y = 1.f / (1.f + __expf(-c[1]));
            v1.x = 1.f / (1.f + __expf(-c[2]));
            v1.y = 1.f / (1.f + __expf(-c[3]));
            *(float2*)&out[r0 * NN + c0] = v0;
            *(float2*)&out[(r0 + 8) * NN + c0] = v1;
        }
    }
}

// ---------------- aux stream/events (created once, on the non-captured first call) ----------------
struct Aux {
    cudaStream_t s2;
    cudaEvent_t  e_fork, e_join;
    Aux() {
        cudaStreamCreateWithFlags(&s2, cudaStreamNonBlocking);
        cudaEventCreateWithFlags(&e_fork, cudaEventDisableTiming);
        cudaEventCreateWithFlags(&e_join, cudaEventDisableTiming);
        cudaFuncSetAttribute((const void*)mma_gemm_pipe<512, 3>,
                             cudaFuncAttributeMaxDynamicSharedMemorySize, 65536);
    }
};
static Aux& aux() { static Aux a; return a; }

// ---------------- launch ----------------
extern "C" void kernel_launch(void* const* d_in, const int* in_sizes, int n_in,
                              void* d_out, int out_size) {
    const int*   edge = (const int*)d_in[0];
    const float* x    = (const float*)d_in[1];
    const float* W1   = (const float*)d_in[2];
    const float* b1   = (const float*)d_in[3];
    const float* Wmu  = (const float*)d_in[4];
    const float* bmu  = (const float*)d_in[5];
    const float* Wlv  = (const float*)d_in[6];
    const float* blv  = (const float*)d_in[7];

    const int* row = edge;
    const int* col = edge + EE;

    float* out     = (float*)d_out;
    float* A_pred  = out;
    float* mu_out  = out + (size_t)NN * NN;
    float* lv_out  = mu_out + (size_t)NN * LAT;
    float* z_out   = lv_out + (size_t)NN * LAT;

    float* h0;   cudaGetSymbolAddress((void**)&h0,   g_h0);
    float* hw;   cudaGetSymbolAddress((void**)&hw,   g_hw);
    __nv_bfloat16* zs;   cudaGetSymbolAddress((void**)&zs,   g_zs);
    __nv_bfloat16* xs;   cudaGetSymbolAddress((void**)&xs,   g_xs);
    __nv_bfloat16* hs;   cudaGetSymbolAddress((void**)&hs,   g_hs);
    __nv_bfloat16* w1s;  cudaGetSymbolAddress((void**)&w1s,  g_w1s);
    __nv_bfloat16* wmls; cudaGetSymbolAddress((void**)&wmls, g_wmls);

    Aux& a = aux();

    // fork: aux stream runs graph preproc in parallel with prep+gemm1
    cudaEventRecord(a.e_fork, 0);
    cudaStreamWaitEvent(a.s2, a.e_fork, 0);
    zero_kernel<<<(NN + 255) / 256, 256, 0, a.s2>>>();
    count_kernel<<<(EE + 255) / 256, 256, 0, a.s2>>>(col);
    scan_kernel<<<1, 1024, 0, a.s2>>>();
    fill_kernel<<<(EE + 255) / 256, 256, 0, a.s2>>>(row, col);
    cudaEventRecord(a.e_join, a.s2);

    // main stream: all splits, then pipelined layer-1 GEMM
    prep_kernel<<<(NN * 512) / 256, 256>>>(x, W1, Wmu, Wlv, xs, w1s, wmls);
    mma_gemm_pipe<512, 3><<<dim3(4, 64), 256, 65536>>>(xs, w1s, h0, 512);

    // join: aggregation needs CSR (aux) + h0 (main)
    cudaStreamWaitEvent(0, a.e_join, 0);
    aggregate_relu_split_kernel<<<NN, 128>>>(h0, b1, hs);

    // layer 2: pipelined gemm2, then aggregate
    mma_gemm_pipe<512, 3><<<dim3(2, 64), 256, 65536>>>(hs, wmls, hw, 256);
    final_agg_kernel<<<NN, 64>>>(hw, bmu, blv, mu_out, z_out, lv_out, zs);

    // decode: A_pred = sigmoid(z z^T), dense
    zzt_mma_kernel<<<dim3(64, 64), 256>>>(zs, A_pred);
}